// round 2
// baseline (speedup 1.0000x reference)
#include <cuda_runtime.h>
#include <math.h>

#define T_DIM 512
#define B_DIM 64
#define I_DIM 512
#define H_DIM 512
#define BH (B_DIM * H_DIM)          // 32768
#define NBLK 128                    // persistent blocks in recurrent kernel
#define NKC 4                       // split-K chunks (512/128)
#define NHG 32                      // h-groups (512/16)

// ---------------- scratch (no allocations allowed) ----------------
__device__ float g_xz[T_DIM * B_DIM];
__device__ float g_xr[T_DIM * B_DIM];
__device__ float g_part[NKC * B_DIM * H_DIM];   // [kc][b][h] partial matvec, 512KB
__device__ float g_azp[NKC * B_DIM];
__device__ float g_arp[NKC * B_DIM];
__device__ unsigned int g_arrive[NBLK];
__device__ unsigned int g_release;

// ---------------- grid-wide barrier: flag array, no atomic pileup ----------------
__device__ __forceinline__ void gsync(unsigned int target) {
    __syncthreads();
    if (blockIdx.x == 0) {
        unsigned int tid = threadIdx.x;
        if (tid > 0 && tid < NBLK) {
            while (((volatile unsigned int*)g_arrive)[tid] < target) { }
        }
        __syncthreads();              // all 127 flags seen -> everyone arrived
        if (tid == 0) {
            __threadfence();
            *(volatile unsigned int*)&g_release = target;
        }
        __syncthreads();
    } else {
        if (threadIdx.x == 0) {
            __threadfence();          // publish this block's phase writes
            ((volatile unsigned int*)g_arrive)[blockIdx.x] = target;
            while (*(volatile unsigned int*)&g_release < target) { }
            __threadfence();
        }
        __syncthreads();
    }
}

// ---------------- K1: xz/xr gate input projections ----------------
__global__ __launch_bounds__(256) void k_gates_x(
    const float* __restrict__ inp,
    const float* __restrict__ zw, const float* __restrict__ zb,
    const float* __restrict__ rw, const float* __restrict__ rb)
{
    int w = (blockIdx.x * blockDim.x + threadIdx.x) >> 5;
    int lane = threadIdx.x & 31;
    if (w >= T_DIM * B_DIM) return;
    const float4* ip = (const float4*)(inp + (size_t)w * I_DIM);
    const float4* zp = (const float4*)zw;
    const float4* rp = (const float4*)rw;
    float az = 0.f, ar = 0.f;
#pragma unroll
    for (int i = 0; i < 4; i++) {
        float4 v = ip[i * 32 + lane];
        float4 a = zp[i * 32 + lane];
        float4 b = rp[i * 32 + lane];
        az += v.x * a.x + v.y * a.y + v.z * a.z + v.w * a.w;
        ar += v.x * b.x + v.y * b.y + v.z * b.z + v.w * b.w;
    }
#pragma unroll
    for (int o = 16; o > 0; o >>= 1) {
        az += __shfl_down_sync(0xffffffffu, az, o);
        ar += __shfl_down_sync(0xffffffffu, ar, o);
    }
    if (lane == 0) {
        g_xz[w] = az + zb[0];
        g_xr[w] = ar + rb[0];
    }
}

// ---------------- K2: xn = input @ h_w_w^T + h_w_b -> out[t] ----------------
// C[32768, 512]; BM=128, BN=64, BK=16, 256 threads, 8x4 micro-tile, reg prefetch
__global__ __launch_bounds__(256) void k_xn(
    const float* __restrict__ A,
    const float* __restrict__ W,
    const float* __restrict__ bias,
    float* __restrict__ C)
{
    __shared__ float As[128 * 17];   // [m][k], stride 17 to break conflicts
    __shared__ float Bs[16 * 64];    // [k][n]
    const int bm = blockIdx.y * 128;
    const int bn = blockIdx.x * 64;
    const int tid = threadIdx.x;
    const int tx = tid & 15;          // n quad (16 * 4 = 64)
    const int ty = tid >> 4;          // m octet (16 * 8 = 128)
    const int r0 = tid >> 2;          // 0..63
    const int c4 = (tid & 3) * 4;     // 0,4,8,12

    float acc[8][4] = {};

    const float* Ap0 = A + (size_t)(bm + r0) * 512 + c4;
    const float* Ap1 = A + (size_t)(bm + r0 + 64) * 512 + c4;
    const float* Wp  = W + (size_t)(bn + r0) * 512 + c4;

    float4 a0 = *(const float4*)Ap0;
    float4 a1 = *(const float4*)Ap1;
    float4 w0 = *(const float4*)Wp;

    for (int kt = 0; kt < 32; kt++) {
        As[r0 * 17 + c4 + 0] = a0.x;  As[r0 * 17 + c4 + 1] = a0.y;
        As[r0 * 17 + c4 + 2] = a0.z;  As[r0 * 17 + c4 + 3] = a0.w;
        As[(r0 + 64) * 17 + c4 + 0] = a1.x;  As[(r0 + 64) * 17 + c4 + 1] = a1.y;
        As[(r0 + 64) * 17 + c4 + 2] = a1.z;  As[(r0 + 64) * 17 + c4 + 3] = a1.w;
        Bs[(c4 + 0) * 64 + r0] = w0.x;  Bs[(c4 + 1) * 64 + r0] = w0.y;
        Bs[(c4 + 2) * 64 + r0] = w0.z;  Bs[(c4 + 3) * 64 + r0] = w0.w;
        __syncthreads();
        if (kt < 31) {
            a0 = *(const float4*)(Ap0 + (kt + 1) * 16);
            a1 = *(const float4*)(Ap1 + (kt + 1) * 16);
            w0 = *(const float4*)(Wp  + (kt + 1) * 16);
        }
#pragma unroll
        for (int k = 0; k < 16; k++) {
            float4 b4 = *(float4*)&Bs[k * 64 + tx * 4];
            float a[8];
#pragma unroll
            for (int i = 0; i < 8; i++) a[i] = As[(ty * 8 + i) * 17 + k];
#pragma unroll
            for (int i = 0; i < 8; i++) {
                acc[i][0] += a[i] * b4.x;
                acc[i][1] += a[i] * b4.y;
                acc[i][2] += a[i] * b4.z;
                acc[i][3] += a[i] * b4.w;
            }
        }
        __syncthreads();
    }
    float4 bv = *(const float4*)(bias + bn + tx * 4);
#pragma unroll
    for (int i = 0; i < 8; i++) {
        float4 o;
        o.x = acc[i][0] + bv.x;
        o.y = acc[i][1] + bv.y;
        o.z = acc[i][2] + bv.z;
        o.w = acc[i][3] + bv.w;
        *(float4*)(C + (size_t)(bm + ty * 8 + i) * 512 + bn + tx * 4) = o;
    }
}

// ---------------- K3: persistent recurrent scan ----------------
// 128 blocks = 32 h-groups (16 cols) x 4 K-chunks (128). Weight chunk persistent
// in SMEM. Per step: A (split-K matvec + gate partials) -> bar -> B (combine +
// gates + update, h kept in register per thread) -> bar.
__global__ __launch_bounds__(256, 1) void k_recur(
    const float* __restrict__ hidden,
    const float* __restrict__ zu_w, const float* __restrict__ zu_b,
    const float* __restrict__ ru_w, const float* __restrict__ ru_b,
    const float* __restrict__ hu_w, const float* __restrict__ hu_b,
    float* __restrict__ out,          // [T][B][H]: xn on entry, h_t on exit
    float* __restrict__ hfinal, int write_final)
{
    __shared__ float w_s[128 * 16];    // [k][j]
    __shared__ float h_s[64 * 132];    // [b][k] padded (stride 132)
    __shared__ float zu_s[512];
    __shared__ float ru_s[512];

    const int tid = threadIdx.x;
    const int bid = blockIdx.x;
    const int hg = bid & 31;           // cols [hg*16, hg*16+16)
    const int kc = bid >> 5;           // k in [kc*128, kc*128+128)
    const int h0 = hg * 16;
    const int k0 = kc * 128;
    const int tx = tid & 3;            // h quad within group
    const int ty = tid >> 2;           // b (0..63)

    // persistent weight chunk, transposed
    for (int e = tid; e < 2048; e += 256) {
        int k = e & 127, j = e >> 7;
        w_s[k * 16 + j] = hu_w[(size_t)(h0 + j) * 512 + k0 + k];
    }
    for (int e = tid; e < 512; e += 256) {
        zu_s[e] = zu_w[e];
        ru_s[e] = ru_w[e];
    }
    const float zub = zu_b[0], rub = ru_b[0];

    const int eidx = bid * 256 + tid;        // 0..32767
    const int eb = eidx >> 9;
    const int eh = eidx & 511;
    const float hub_e = hu_b[eh];
    float hreg = hidden[eidx];               // this thread's h element

    const unsigned int base = *(volatile unsigned int*)&g_release;
    __syncthreads();

    for (int t = 0; t < T_DIM; t++) {
        const float* hprev = (t == 0) ? hidden : (out + (size_t)(t - 1) * BH);

        // ---- phase A: load h chunk [64 b][128 k] (coalesced float4) ----
        const float* hp = hprev + k0;
#pragma unroll
        for (int i = 0; i < 8; i++) {
            int e4 = tid + i * 256;
            int b = e4 >> 5, kq = e4 & 31;
            float4 v = *(const float4*)(hp + (size_t)b * 512 + kq * 4);
            *(float4*)&h_s[b * 132 + kq * 4] = v;
        }
        __syncthreads();

        // gate partials: 4 blocks (hg==0), one per K-chunk
        if (hg == 0 && tid < 64) {
            float az = 0.f, ar = 0.f;
#pragma unroll 16
            for (int k = 0; k < 128; k++) {
                float hv = h_s[tid * 132 + k];
                az += hv * zu_s[k0 + k];
                ar += hv * ru_s[k0 + k];
            }
            g_azp[kc * 64 + tid] = az;
            g_arp[kc * 64 + tid] = ar;
        }

        // split-K partial of h @ hu_w^T : 1x4 micro-tile
        float acc0 = 0.f, acc1 = 0.f, acc2 = 0.f, acc3 = 0.f;
#pragma unroll 16
        for (int k = 0; k < 128; k++) {
            float hv = h_s[ty * 132 + k];
            float4 wv = *(float4*)&w_s[k * 16 + tx * 4];
            acc0 += hv * wv.x;
            acc1 += hv * wv.y;
            acc2 += hv * wv.z;
            acc3 += hv * wv.w;
        }
        *(float4*)&g_part[((size_t)kc * 64 + ty) * 512 + h0 + tx * 4] =
            make_float4(acc0, acc1, acc2, acc3);

        gsync(base + 2 * t + 1);

        // ---- phase B: combine 4 partials, gates, state update ----
        {
            float az = g_xz[t * 64 + eb] + zub;
            float ar = g_xr[t * 64 + eb] + rub;
            float m = hub_e;
#pragma unroll
            for (int kk = 0; kk < NKC; kk++) {
                az += g_azp[kk * 64 + eb];
                ar += g_arp[kk * 64 + eb];
                m  += g_part[((size_t)kk * 64 + eb) * 512 + eh];
            }
            float z = 1.0f / (1.0f + __expf(-az));
            float r = 1.0f / (1.0f + __expf(-ar));
            float xn = out[(size_t)t * BH + eidx];          // precomputed xn
            float arg = xn + m * r;
            arg = fminf(fmaxf(arg, -15.0f), 15.0f);
            float e2 = __expf(2.0f * arg);
            float n = 1.0f - 2.0f / (e2 + 1.0f);
            hreg = (1.0f - z) * n + z * hreg;
            out[(size_t)t * BH + eidx] = hreg;              // overwrite with h_t
        }

        gsync(base + 2 * t + 2);
    }

    if (write_final)
        hfinal[eidx] = hreg;
}

// ---------------- launcher ----------------
extern "C" void kernel_launch(void* const* d_in, const int* in_sizes, int n_in,
                              void* d_out, int out_size)
{
    const float* input  = (const float*)d_in[0];
    const float* hidden = (const float*)d_in[1];
    const float* zt_w_w = (const float*)d_in[2];
    const float* zt_w_b = (const float*)d_in[3];
    const float* zt_u_w = (const float*)d_in[4];
    const float* zt_u_b = (const float*)d_in[5];
    const float* rt_w_w = (const float*)d_in[6];
    const float* rt_w_b = (const float*)d_in[7];
    const float* rt_u_w = (const float*)d_in[8];
    const float* rt_u_b = (const float*)d_in[9];
    const float* h_w_w  = (const float*)d_in[10];
    const float* h_w_b  = (const float*)d_in[11];
    const float* h_u_w  = (const float*)d_in[12];
    const float* h_u_b  = (const float*)d_in[13];

    float* out = (float*)d_out;
    int wf = (out_size >= T_DIM * BH + BH) ? 1 : 0;
    float* hfin = out + (size_t)T_DIM * BH;

    k_gates_x<<<4096, 256>>>(input, zt_w_w, zt_w_b, rt_w_w, rt_w_b);
    k_xn<<<dim3(8, 256), 256>>>(input, h_w_w, h_w_b, out);
    k_recur<<<NBLK, 256>>>(hidden, zt_u_w, zt_u_b, rt_u_w, rt_u_b,
                           h_u_w, h_u_b, out, hfin, wf);
}

// round 3
// speedup vs baseline: 1.0902x; 1.0902x over previous
#include <cuda_runtime.h>
#include <math.h>

#define T_DIM 512
#define B_DIM 64
#define I_DIM 512
#define H_DIM 512
#define BH (B_DIM * H_DIM)          // 32768
#define NBLK 128                    // persistent blocks in recurrent kernel
#define NKC 16                      // split-K chunks (512/32)
#define NHG 8                       // h-groups (64 cols each)

// ---------------- scratch (no allocations allowed) ----------------
__device__ float g_xz[T_DIM * B_DIM];
__device__ float g_xr[T_DIM * B_DIM];
__device__ float g_part[NKC * B_DIM * H_DIM];   // [kc][b][h] partials, 2MB
__device__ float g_azp[NKC * B_DIM];
__device__ float g_arp[NKC * B_DIM];
__device__ unsigned int g_flag[NBLK * 8];       // sector-padded flags (32B apart)

// ---------------- release/acquire helpers ----------------
__device__ __forceinline__ void st_rel(unsigned int* p, unsigned int v) {
    asm volatile("st.release.gpu.global.u32 [%0], %1;" :: "l"(p), "r"(v) : "memory");
}
__device__ __forceinline__ unsigned int ld_acq(unsigned int* p) {
    unsigned int v;
    asm volatile("ld.acquire.gpu.global.u32 %0, [%1];" : "=r"(v) : "l"(p) : "memory");
    return v;
}

// symmetric all-poll grid barrier: 1 release store + 128 parallel acquire polls
__device__ __forceinline__ void gsync(int bid, int tid, unsigned int target) {
    __syncthreads();
    if (tid == 0) st_rel(&g_flag[bid * 8], target);
    if (tid < NBLK) {
        while (ld_acq(&g_flag[tid * 8]) < target) { }
    }
    __syncthreads();
}

// ---------------- K1: xz/xr gate input projections ----------------
__global__ __launch_bounds__(256) void k_gates_x(
    const float* __restrict__ inp,
    const float* __restrict__ zw, const float* __restrict__ zb,
    const float* __restrict__ rw, const float* __restrict__ rb)
{
    int w = (blockIdx.x * blockDim.x + threadIdx.x) >> 5;
    int lane = threadIdx.x & 31;
    if (w >= T_DIM * B_DIM) return;
    const float4* ip = (const float4*)(inp + (size_t)w * I_DIM);
    const float4* zp = (const float4*)zw;
    const float4* rp = (const float4*)rw;
    float az = 0.f, ar = 0.f;
#pragma unroll
    for (int i = 0; i < 4; i++) {
        float4 v = ip[i * 32 + lane];
        float4 a = zp[i * 32 + lane];
        float4 b = rp[i * 32 + lane];
        az += v.x * a.x + v.y * a.y + v.z * a.z + v.w * a.w;
        ar += v.x * b.x + v.y * b.y + v.z * b.z + v.w * b.w;
    }
#pragma unroll
    for (int o = 16; o > 0; o >>= 1) {
        az += __shfl_down_sync(0xffffffffu, az, o);
        ar += __shfl_down_sync(0xffffffffu, ar, o);
    }
    if (lane == 0) {
        g_xz[w] = az + zb[0];
        g_xr[w] = ar + rb[0];
    }
}

// ---------------- K2: xn = input @ h_w_w^T + h_w_b -> out[t] ----------------
// BM=128, BN=64, BK=16, 256 threads, 8x4 micro-tile, register prefetch
__global__ __launch_bounds__(256) void k_xn(
    const float* __restrict__ A,
    const float* __restrict__ W,
    const float* __restrict__ bias,
    float* __restrict__ C)
{
    __shared__ float As[128 * 17];
    __shared__ float Bs[16 * 64];
    const int bm = blockIdx.y * 128;
    const int bn = blockIdx.x * 64;
    const int tid = threadIdx.x;
    const int tx = tid & 15;
    const int ty = tid >> 4;
    const int r0 = tid >> 2;
    const int c4 = (tid & 3) * 4;

    float acc[8][4] = {};

    const float* Ap0 = A + (size_t)(bm + r0) * 512 + c4;
    const float* Ap1 = A + (size_t)(bm + r0 + 64) * 512 + c4;
    const float* Wp  = W + (size_t)(bn + r0) * 512 + c4;

    float4 a0 = *(const float4*)Ap0;
    float4 a1 = *(const float4*)Ap1;
    float4 w0 = *(const float4*)Wp;

    for (int kt = 0; kt < 32; kt++) {
        As[r0 * 17 + c4 + 0] = a0.x;  As[r0 * 17 + c4 + 1] = a0.y;
        As[r0 * 17 + c4 + 2] = a0.z;  As[r0 * 17 + c4 + 3] = a0.w;
        As[(r0 + 64) * 17 + c4 + 0] = a1.x;  As[(r0 + 64) * 17 + c4 + 1] = a1.y;
        As[(r0 + 64) * 17 + c4 + 2] = a1.z;  As[(r0 + 64) * 17 + c4 + 3] = a1.w;
        Bs[(c4 + 0) * 64 + r0] = w0.x;  Bs[(c4 + 1) * 64 + r0] = w0.y;
        Bs[(c4 + 2) * 64 + r0] = w0.z;  Bs[(c4 + 3) * 64 + r0] = w0.w;
        __syncthreads();
        if (kt < 31) {
            a0 = *(const float4*)(Ap0 + (kt + 1) * 16);
            a1 = *(const float4*)(Ap1 + (kt + 1) * 16);
            w0 = *(const float4*)(Wp  + (kt + 1) * 16);
        }
#pragma unroll
        for (int k = 0; k < 16; k++) {
            float4 b4 = *(float4*)&Bs[k * 64 + tx * 4];
            float a[8];
#pragma unroll
            for (int i = 0; i < 8; i++) a[i] = As[(ty * 8 + i) * 17 + k];
#pragma unroll
            for (int i = 0; i < 8; i++) {
                acc[i][0] += a[i] * b4.x;
                acc[i][1] += a[i] * b4.y;
                acc[i][2] += a[i] * b4.z;
                acc[i][3] += a[i] * b4.w;
            }
        }
        __syncthreads();
    }
    float4 bv = *(const float4*)(bias + bn + tx * 4);
#pragma unroll
    for (int i = 0; i < 8; i++) {
        float4 o;
        o.x = acc[i][0] + bv.x;
        o.y = acc[i][1] + bv.y;
        o.z = acc[i][2] + bv.z;
        o.w = acc[i][3] + bv.w;
        *(float4*)(C + (size_t)(bm + ty * 8 + i) * 512 + bn + tx * 4) = o;
    }
}

// ---------------- K3: persistent recurrent scan ----------------
// 128 blocks = 8 h-groups (64 cols) x 16 K-chunks (32 k). 4x4 micro-tile
// (2 B LDS per FMA, FMA-floor-bound). Two fast all-poll barriers per step.
__global__ __launch_bounds__(256, 1) void k_recur(
    const float* __restrict__ hidden,
    const float* __restrict__ zu_w, const float* __restrict__ zu_b,
    const float* __restrict__ ru_w, const float* __restrict__ ru_b,
    const float* __restrict__ hu_w, const float* __restrict__ hu_b,
    float* __restrict__ out,          // [T][B][H]: xn on entry, h_t on exit
    float* __restrict__ hfinal, int write_final)
{
    __shared__ float w_s[32 * 64];     // [k][j] transposed weight chunk
    __shared__ float h_s[64 * 36];     // [b][k] padded
    __shared__ float zu_s[512];
    __shared__ float ru_s[512];

    const int tid = threadIdx.x;
    const int bid = blockIdx.x;
    const int hg = bid & 7;            // cols [hg*64, hg*64+64)
    const int kc = bid >> 3;           // k in [kc*32, kc*32+32)
    const int h0 = hg * 64;
    const int k0 = kc * 32;
    const int tx = tid & 15;           // h quad
    const int ty = tid >> 4;           // b quad

    // persistent transposed weight tile
    for (int e = tid; e < 2048; e += 256) {
        int j = e >> 5, k = e & 31;
        w_s[k * 64 + j] = hu_w[(size_t)(h0 + j) * 512 + k0 + k];
    }
    for (int e = tid; e < 512; e += 256) {
        zu_s[e] = zu_w[e];
        ru_s[e] = ru_w[e];
    }
    const float zub = zu_b[0], rub = ru_b[0];

    const int eidx = bid * 256 + tid;        // element this thread owns in phase B
    const int eb = eidx >> 9;
    const int eh = eidx & 511;
    const float hub_e = hu_b[eh];
    float hreg = hidden[eidx];

    const unsigned int base = g_flag[bid * 8];   // all equal across launches
    __syncthreads();

    for (int t = 0; t < T_DIM; t++) {
        const float* hprev = (t == 0) ? hidden : (out + (size_t)(t - 1) * BH);

        // prefetch step-t-stable per-thread inputs (hidden by phase A compute)
        float xn_pf  = __ldcg(out + (size_t)t * BH + eidx);
        float azx_pf = g_xz[t * 64 + eb];
        float arx_pf = g_xr[t * 64 + eb];

        // ---- phase A: load h chunk [64 b][32 k] as float4 ----
        const float* hp = hprev + k0;
#pragma unroll
        for (int i = 0; i < 2; i++) {
            int e4 = tid + i * 256;              // 512 float4 total
            int b = e4 >> 3, kq = e4 & 7;
            float4 v = *(const float4*)(hp + (size_t)b * 512 + kq * 4);
            *(float4*)&h_s[b * 36 + kq * 4] = v;
        }
        __syncthreads();

        // gate partials (hg==0 blocks: 16 blocks cover 16 K-chunks)
        if (hg == 0 && tid < 64) {
            float az = 0.f, ar = 0.f;
#pragma unroll
            for (int k = 0; k < 32; k++) {
                float hv = h_s[tid * 36 + k];
                az += hv * zu_s[k0 + k];
                ar += hv * ru_s[k0 + k];
            }
            g_azp[kc * 64 + tid] = az;
            g_arp[kc * 64 + tid] = ar;
        }

        // split-K partial matvec: 4x4 register tile
        float acc[4][4] = {};
#pragma unroll
        for (int k = 0; k < 32; k++) {
            float4 wv = *(float4*)&w_s[k * 64 + tx * 4];
            float hv0 = h_s[(ty * 4 + 0) * 36 + k];
            float hv1 = h_s[(ty * 4 + 1) * 36 + k];
            float hv2 = h_s[(ty * 4 + 2) * 36 + k];
            float hv3 = h_s[(ty * 4 + 3) * 36 + k];
            acc[0][0] += hv0 * wv.x; acc[0][1] += hv0 * wv.y;
            acc[0][2] += hv0 * wv.z; acc[0][3] += hv0 * wv.w;
            acc[1][0] += hv1 * wv.x; acc[1][1] += hv1 * wv.y;
            acc[1][2] += hv1 * wv.z; acc[1][3] += hv1 * wv.w;
            acc[2][0] += hv2 * wv.x; acc[2][1] += hv2 * wv.y;
            acc[2][2] += hv2 * wv.z; acc[2][3] += hv2 * wv.w;
            acc[3][0] += hv3 * wv.x; acc[3][1] += hv3 * wv.y;
            acc[3][2] += hv3 * wv.z; acc[3][3] += hv3 * wv.w;
        }
#pragma unroll
        for (int i = 0; i < 4; i++) {
            *(float4*)&g_part[((size_t)kc * 64 + ty * 4 + i) * 512 + h0 + tx * 4] =
                make_float4(acc[i][0], acc[i][1], acc[i][2], acc[i][3]);
        }

        gsync(bid, tid, base + 2 * t + 1);

        // ---- phase B: combine 16 partials, gates, state update ----
        {
            float az = azx_pf + zub;
            float ar = arx_pf + rub;
            float m = hub_e;
#pragma unroll
            for (int kk = 0; kk < NKC; kk++) {
                az += g_azp[kk * 64 + eb];
                ar += g_arp[kk * 64 + eb];
                m  += g_part[((size_t)kk * 64 + eb) * 512 + eh];
            }
            float z = 1.0f / (1.0f + __expf(-az));
            float r = 1.0f / (1.0f + __expf(-ar));
            float arg = xn_pf + m * r;
            arg = fminf(fmaxf(arg, -15.0f), 15.0f);
            float e2 = __expf(2.0f * arg);
            float n = 1.0f - 2.0f / (e2 + 1.0f);
            hreg = (1.0f - z) * n + z * hreg;
            out[(size_t)t * BH + eidx] = hreg;
        }

        gsync(bid, tid, base + 2 * t + 2);
    }

    if (write_final)
        hfinal[eidx] = hreg;
}

// ---------------- launcher ----------------
extern "C" void kernel_launch(void* const* d_in, const int* in_sizes, int n_in,
                              void* d_out, int out_size)
{
    const float* input  = (const float*)d_in[0];
    const float* hidden = (const float*)d_in[1];
    const float* zt_w_w = (const float*)d_in[2];
    const float* zt_w_b = (const float*)d_in[3];
    const float* zt_u_w = (const float*)d_in[4];
    const float* zt_u_b = (const float*)d_in[5];
    const float* rt_w_w = (const float*)d_in[6];
    const float* rt_w_b = (const float*)d_in[7];
    const float* rt_u_w = (const float*)d_in[8];
    const float* rt_u_b = (const float*)d_in[9];
    const float* h_w_w  = (const float*)d_in[10];
    const float* h_w_b  = (const float*)d_in[11];
    const float* h_u_w  = (const float*)d_in[12];
    const float* h_u_b  = (const float*)d_in[13];

    float* out = (float*)d_out;
    int wf = (out_size >= T_DIM * BH + BH) ? 1 : 0;
    float* hfin = out + (size_t)T_DIM * BH;

    k_gates_x<<<4096, 256>>>(input, zt_w_w, zt_w_b, rt_w_w, rt_w_b);
    k_xn<<<dim3(8, 256), 256>>>(input, h_w_w, h_w_b, out);
    k_recur<<<NBLK, 256>>>(hidden, zt_u_w, zt_u_b, rt_u_w, rt_u_b,
                           h_u_w, h_u_b, out, hfin, wf);
}

// round 6
// speedup vs baseline: 1.5823x; 1.4514x over previous
#include <cuda_runtime.h>
#include <math.h>

#define T_DIM 512
#define B_DIM 64
#define I_DIM 512
#define H_DIM 512
#define BH (B_DIM * H_DIM)          // 32768
#define NBLK 128                    // persistent blocks in recurrent kernel
#define NKC 16                      // split-K chunks (512/32)

// ---------------- scratch (no allocations allowed) ----------------
__device__ float g_part[NKC * B_DIM * H_DIM];   // [kc][b][h] partials, 2MB
__device__ float g_azp[NKC * B_DIM];
__device__ float g_arp[NKC * B_DIM];
__device__ unsigned int g_ctr;                  // barrier counter (reset at end)

// ---------------- packed f32x2 helpers ----------------
static __device__ __forceinline__ unsigned long long pk2(float x) {
    unsigned long long r;
    asm("mov.b64 %0, {%1, %1};" : "=l"(r) : "f"(x));
    return r;
}
static __device__ __forceinline__ void fma2(unsigned long long& d,
                                            unsigned long long a,
                                            unsigned long long b) {
    asm("fma.rn.f32x2 %0, %1, %2, %0;" : "+l"(d) : "l"(a), "l"(b));
}
static __device__ __forceinline__ void unpk(unsigned long long v,
                                            float& lo, float& hi) {
    asm("mov.b64 {%0, %1}, %2;" : "=f"(lo), "=f"(hi) : "l"(v));
}

// ---------------- barrier primitives ----------------
static __device__ __forceinline__ void arrive_rel() {
    unsigned int* p = &g_ctr;
    asm volatile("red.release.gpu.global.add.u32 [%0], 1;" :: "l"(p) : "memory");
}
static __device__ __forceinline__ unsigned int ld_acq_ctr() {
    unsigned int v;
    unsigned int* p = &g_ctr;
    asm volatile("ld.acquire.gpu.global.u32 %0, [%1];" : "=r"(v) : "l"(p) : "memory");
    return v;
}
// grid barrier: 1 red.release arrival + single-thread acquire poll + bar.sync
static __device__ __forceinline__ void gsync(int tid, unsigned int target) {
    __syncthreads();
    if (tid == 0) {
        arrive_rel();
        while (ld_acq_ctr() < target) { }
    }
    __syncthreads();
}

// ---------------- K1: xn = input @ h_w_w^T + h_w_b -> out[t] ----------------
// BM=BN=64, BK=16, 256 threads, 4x4 micro-tile via packed f32x2
__global__ __launch_bounds__(256) void k_xn(
    const float* __restrict__ A,
    const float* __restrict__ W,
    const float* __restrict__ bias,
    float* __restrict__ C)
{
    __shared__ float As[64 * 17];
    __shared__ float Bs[16 * 64];
    const int bm = blockIdx.y * 64;
    const int bn = blockIdx.x * 64;
    const int tid = threadIdx.x;
    const int tx = tid & 15;
    const int ty = tid >> 4;
    const int r0 = tid >> 2;
    const int c4 = (tid & 3) * 4;

    unsigned long long acc[4][2] = {};

    const float* Ap = A + (size_t)(bm + r0) * 512 + c4;
    const float* Wp = W + (size_t)(bn + r0) * 512 + c4;
    float4 a0 = *(const float4*)Ap;
    float4 w0 = *(const float4*)Wp;

    for (int kt = 0; kt < 32; kt++) {
        As[r0 * 17 + c4 + 0] = a0.x;  As[r0 * 17 + c4 + 1] = a0.y;
        As[r0 * 17 + c4 + 2] = a0.z;  As[r0 * 17 + c4 + 3] = a0.w;
        Bs[(c4 + 0) * 64 + r0] = w0.x;  Bs[(c4 + 1) * 64 + r0] = w0.y;
        Bs[(c4 + 2) * 64 + r0] = w0.z;  Bs[(c4 + 3) * 64 + r0] = w0.w;
        __syncthreads();
        if (kt < 31) {
            a0 = *(const float4*)(Ap + (kt + 1) * 16);
            w0 = *(const float4*)(Wp + (kt + 1) * 16);
        }
#pragma unroll
        for (int k = 0; k < 16; k++) {
            ulonglong2 b2 = *(ulonglong2*)&Bs[k * 64 + tx * 4];
#pragma unroll
            for (int i = 0; i < 4; i++) {
                unsigned long long aa = pk2(As[(ty * 4 + i) * 17 + k]);
                fma2(acc[i][0], aa, b2.x);
                fma2(acc[i][1], aa, b2.y);
            }
        }
        __syncthreads();
    }
    float4 bv = *(const float4*)(bias + bn + tx * 4);
#pragma unroll
    for (int i = 0; i < 4; i++) {
        float x0, x1, x2, x3;
        unpk(acc[i][0], x0, x1);
        unpk(acc[i][1], x2, x3);
        float4 o = make_float4(x0 + bv.x, x1 + bv.y, x2 + bv.z, x3 + bv.w);
        *(float4*)(C + (size_t)(bm + ty * 4 + i) * 512 + bn + tx * 4) = o;
    }
}

// ---------------- K2: persistent recurrent scan ----------------
// 128 blocks = 8 h-groups (64 cols) x 16 K-chunks (32 k). Preamble computes this
// block's xz/xr for all t (its single batch row). Per step: phase A (f32x2
// split-K matvec) -> gsync -> phase B (combine + gates + update) -> gsync.
__global__ __launch_bounds__(256, 1) void k_recur(
    const float* __restrict__ input,
    const float* __restrict__ hidden,
    const float* __restrict__ zw_w, const float* __restrict__ zw_b,
    const float* __restrict__ zu_w, const float* __restrict__ zu_b,
    const float* __restrict__ rw_w, const float* __restrict__ rw_b,
    const float* __restrict__ ru_w, const float* __restrict__ ru_b,
    const float* __restrict__ hu_w, const float* __restrict__ hu_b,
    float* __restrict__ out,          // [T][B][H]: xn on entry, h_t on exit
    float* __restrict__ hfinal, int write_final)
{
    __shared__ float w_s[32 * 64];     // [k][j] transposed weight chunk (8KB)
    __shared__ float h_s[64 * 36];     // [b][k] padded (9.2KB)
    __shared__ float zu_s[512];
    __shared__ float ru_s[512];
    __shared__ float zw_s[512];
    __shared__ float rw_s[512];
    __shared__ float xz_s[T_DIM];      // this block's b-row gate-x, all t
    __shared__ float xr_s[T_DIM];

    const int tid = threadIdx.x;
    const int bid = blockIdx.x;
    const int hg = bid & 7;            // cols [hg*64, hg*64+64)
    const int kc = bid >> 3;           // k in [kc*32, kc*32+32)
    const int h0 = hg * 64;
    const int k0 = kc * 32;
    const int tx = tid & 15;           // h quad
    const int ty = tid >> 4;           // b quad

    const int eidx = bid * 256 + tid;  // phase-B element
    const int eb = bid >> 1;           // batch row (constant per block)
    const int eh = eidx & 511;

    // persistent weights + gate vectors into smem
    for (int e = tid; e < 2048; e += 256) {
        int j = e >> 5, k = e & 31;
        w_s[k * 64 + j] = hu_w[(size_t)(h0 + j) * 512 + k0 + k];
    }
    for (int e = tid; e < 512; e += 256) {
        zu_s[e] = zu_w[e];
        ru_s[e] = ru_w[e];
        zw_s[e] = zw_w[e];
        rw_s[e] = rw_w[e];
    }
    const float zub = zu_b[0], rub = ru_b[0];
    const float zwb = zw_b[0], rwb = rw_b[0];
    const float hub_e = hu_b[eh];
    float hreg = hidden[eidx];
    __syncthreads();

    // preamble: xz/xr for this block's batch row, all 512 timesteps
#pragma unroll 1
    for (int rep = 0; rep < 2; rep++) {
        int t = tid + rep * 256;
        const float4* ip = (const float4*)(input + ((size_t)t * 64 + eb) * 512);
        float az = 0.f, ar = 0.f;
#pragma unroll 8
        for (int i = 0; i < 128; i++) {
            float4 v = ip[i];
            float4 zz = *(float4*)&zw_s[i * 4];
            float4 rr = *(float4*)&rw_s[i * 4];
            az += v.x * zz.x + v.y * zz.y + v.z * zz.z + v.w * zz.w;
            ar += v.x * rr.x + v.y * rr.y + v.z * rr.z + v.w * rr.w;
        }
        xz_s[t] = az + zwb;
        xr_s[t] = ar + rwb;
    }
    __syncthreads();

    for (int t = 0; t < T_DIM; t++) {
        const float* hprev = (t == 0) ? hidden : (out + (size_t)(t - 1) * BH);

        // prefetch this thread's xn (stable until phase B writes it)
        float xn_pf = __ldcg(out + (size_t)t * BH + eidx);

        // ---- phase A: stage h chunk [64 b][32 k] via L2 ----
        const float* hp = hprev + k0;
#pragma unroll
        for (int i = 0; i < 2; i++) {
            int e4 = tid + i * 256;              // 512 float4
            int b = e4 >> 3, kq = e4 & 7;
            float4 v = __ldcg((const float4*)(hp + (size_t)b * 512 + kq * 4));
            *(float4*)&h_s[b * 36 + kq * 4] = v;
        }
        __syncthreads();

        // gate-u partials (hg==0 blocks cover the 16 K-chunks)
        if (hg == 0 && tid < 64) {
            float az = 0.f, ar = 0.f;
#pragma unroll
            for (int k = 0; k < 32; k++) {
                float hv = h_s[tid * 36 + k];
                az += hv * zu_s[k0 + k];
                ar += hv * ru_s[k0 + k];
            }
            g_azp[kc * 64 + tid] = az;
            g_arp[kc * 64 + tid] = ar;
        }

        // split-K partial matvec: 4x4 tile via packed f32x2
        unsigned long long acc[4][2] = {};
#pragma unroll
        for (int k = 0; k < 32; k++) {
            ulonglong2 w2 = *(ulonglong2*)&w_s[k * 64 + tx * 4];
#pragma unroll
            for (int i = 0; i < 4; i++) {
                unsigned long long hh = pk2(h_s[(ty * 4 + i) * 36 + k]);
                fma2(acc[i][0], hh, w2.x);
                fma2(acc[i][1], hh, w2.y);
            }
        }
#pragma unroll
        for (int i = 0; i < 4; i++) {
            float x0, x1, x2, x3;
            unpk(acc[i][0], x0, x1);
            unpk(acc[i][1], x2, x3);
            *(float4*)&g_part[((size_t)kc * 64 + ty * 4 + i) * 512 + h0 + tx * 4] =
                make_float4(x0, x1, x2, x3);
        }

        gsync(tid, (unsigned int)NBLK * (2 * t + 1));

        // ---- phase B: combine 16 partials, gates, state update ----
        {
            float az = xz_s[t] + zub;
            float ar = xr_s[t] + rub;
            float m = hub_e;
#pragma unroll
            for (int kk = 0; kk < NKC; kk++) {
                az += __ldcg(&g_azp[kk * 64 + eb]);
                ar += __ldcg(&g_arp[kk * 64 + eb]);
                m  += __ldcg(&g_part[((size_t)kk * 64 + eb) * 512 + eh]);
            }
            float z = 1.0f / (1.0f + __expf(-az));
            float r = 1.0f / (1.0f + __expf(-ar));
            float arg = xn_pf + m * r;
            arg = fminf(fmaxf(arg, -15.0f), 15.0f);
            float e2 = __expf(2.0f * arg);
            float n = 1.0f - 2.0f / (e2 + 1.0f);
            hreg = (1.0f - z) * n + z * hreg;
            out[(size_t)t * BH + eidx] = hreg;
        }

        gsync(tid, (unsigned int)NBLK * (2 * t + 2));
    }

    if (write_final)
        hfinal[eidx] = hreg;

    // reset barrier counter for graph-replay determinism
    __syncthreads();
    if (tid == 0) {
        arrive_rel();                       // counts to NBLK*2T + NBLK
        if (bid == 0) {
            unsigned int fin = (unsigned int)NBLK * (2 * T_DIM) + NBLK;
            while (ld_acq_ctr() < fin) { }
            unsigned int* p = &g_ctr;
            asm volatile("st.relaxed.gpu.global.u32 [%0], 0;" :: "l"(p) : "memory");
        }
    }
}

// ---------------- launcher ----------------
extern "C" void kernel_launch(void* const* d_in, const int* in_sizes, int n_in,
                              void* d_out, int out_size)
{
    const float* input  = (const float*)d_in[0];
    const float* hidden = (const float*)d_in[1];
    const float* zt_w_w = (const float*)d_in[2];
    const float* zt_w_b = (const float*)d_in[3];
    const float* zt_u_w = (const float*)d_in[4];
    const float* zt_u_b = (const float*)d_in[5];
    const float* rt_w_w = (const float*)d_in[6];
    const float* rt_w_b = (const float*)d_in[7];
    const float* rt_u_w = (const float*)d_in[8];
    const float* rt_u_b = (const float*)d_in[9];
    const float* h_w_w  = (const float*)d_in[10];
    const float* h_w_b  = (const float*)d_in[11];
    const float* h_u_w  = (const float*)d_in[12];
    const float* h_u_b  = (const float*)d_in[13];

    float* out = (float*)d_out;
    int wf = (out_size >= T_DIM * BH + BH) ? 1 : 0;
    float* hfin = out + (size_t)T_DIM * BH;

    k_xn<<<dim3(8, 512), 256>>>(input, h_w_w, h_w_b, out);
    k_recur<<<NBLK, 256>>>(input, hidden,
                           zt_w_w, zt_w_b, zt_u_w, zt_u_b,
                           rt_w_w, rt_w_b, rt_u_w, rt_u_b,
                           h_u_w, h_u_b, out, hfin, wf);
}

// round 8
// speedup vs baseline: 2.2187x; 1.4022x over previous
#include <cuda_runtime.h>
#include <math.h>

#define T_DIM 512
#define B_DIM 64
#define I_DIM 512
#define H_DIM 512
#define BH (B_DIM * H_DIM)          // 32768
#define NBLK 128

// SMEM float offsets (dynamic shared)
#define W_OFF   0                    // 512*68 = 34816 (weight slice, transposed, padded)
#define H_OFF   34816                // 4*520  = 2080  (h rows)
#define RED_OFF 36896                // 16*4*64 = 4096 (k-partials; reused for zw/rw in preamble)
#define ZU_OFF  40992                // 512
#define RU_OFF  41504                // 512
#define XZ_OFF  42016                // 2048 ([t*4+b])
#define XR_OFF  44064                // 2048
#define GZ_OFF  46112                // 64 ([b*16+kc])
#define GR_OFF  46176                // 64
#define SMEM_FLOATS 46240
#define SMEM_BYTES (SMEM_FLOATS * 4) // 184960

// ---------------- scratch ----------------
__device__ float g_xz[T_DIM * B_DIM];
__device__ float g_xr[T_DIM * B_DIM];
__device__ unsigned int g_ctr;

// ---------------- packed f32x2 helpers ----------------
static __device__ __forceinline__ unsigned long long pk2(float x) {
    unsigned long long r;
    asm("mov.b64 %0, {%1, %1};" : "=l"(r) : "f"(x));
    return r;
}
static __device__ __forceinline__ void fma2(unsigned long long& d,
                                            unsigned long long a,
                                            unsigned long long b) {
    asm("fma.rn.f32x2 %0, %1, %2, %0;" : "+l"(d) : "l"(a), "l"(b));
}
static __device__ __forceinline__ void unpk(unsigned long long v,
                                            float& lo, float& hi) {
    asm("mov.b64 {%0, %1}, %2;" : "=f"(lo), "=f"(hi) : "l"(v));
}

// ---------------- barrier ----------------
static __device__ __forceinline__ void arrive_rel() {
    unsigned int* p = &g_ctr;
    asm volatile("red.release.gpu.global.add.u32 [%0], 1;" :: "l"(p) : "memory");
}
static __device__ __forceinline__ unsigned int ld_acq_ctr() {
    unsigned int v;
    unsigned int* p = &g_ctr;
    asm volatile("ld.acquire.gpu.global.u32 %0, [%1];" : "=r"(v) : "l"(p) : "memory");
    return v;
}
static __device__ __forceinline__ void gsync(int tid, unsigned int target) {
    __syncthreads();
    if (tid == 0) {
        arrive_rel();
        while (ld_acq_ctr() < target) { }
    }
    __syncthreads();
}

// ---------------- K1: xn = input @ h_w_w^T + h_w_b -> out[t] ----------------
__global__ __launch_bounds__(256) void k_xn(
    const float* __restrict__ A,
    const float* __restrict__ W,
    const float* __restrict__ bias,
    float* __restrict__ C)
{
    __shared__ float As[64 * 17];
    __shared__ float Bs[16 * 64];
    const int bm = blockIdx.y * 64;
    const int bn = blockIdx.x * 64;
    const int tid = threadIdx.x;
    const int tx = tid & 15;
    const int ty = tid >> 4;
    const int r0 = tid >> 2;
    const int c4 = (tid & 3) * 4;

    unsigned long long acc[4][2] = {};

    const float* Ap = A + (size_t)(bm + r0) * 512 + c4;
    const float* Wp = W + (size_t)(bn + r0) * 512 + c4;
    float4 a0 = *(const float4*)Ap;
    float4 w0 = *(const float4*)Wp;

    for (int kt = 0; kt < 32; kt++) {
        As[r0 * 17 + c4 + 0] = a0.x;  As[r0 * 17 + c4 + 1] = a0.y;
        As[r0 * 17 + c4 + 2] = a0.z;  As[r0 * 17 + c4 + 3] = a0.w;
        Bs[(c4 + 0) * 64 + r0] = w0.x;  Bs[(c4 + 1) * 64 + r0] = w0.y;
        Bs[(c4 + 2) * 64 + r0] = w0.z;  Bs[(c4 + 3) * 64 + r0] = w0.w;
        __syncthreads();
        if (kt < 31) {
            a0 = *(const float4*)(Ap + (kt + 1) * 16);
            w0 = *(const float4*)(Wp + (kt + 1) * 16);
        }
#pragma unroll
        for (int k = 0; k < 16; k++) {
            ulonglong2 b2 = *(ulonglong2*)&Bs[k * 64 + tx * 4];
#pragma unroll
            for (int i = 0; i < 4; i++) {
                unsigned long long aa = pk2(As[(ty * 4 + i) * 17 + k]);
                fma2(acc[i][0], aa, b2.x);
                fma2(acc[i][1], aa, b2.y);
            }
        }
        __syncthreads();
    }
    float4 bv = *(const float4*)(bias + bn + tx * 4);
#pragma unroll
    for (int i = 0; i < 4; i++) {
        float x0, x1, x2, x3;
        unpk(acc[i][0], x0, x1);
        unpk(acc[i][1], x2, x3);
        float4 o = make_float4(x0 + bv.x, x1 + bv.y, x2 + bv.z, x3 + bv.w);
        *(float4*)(C + (size_t)(bm + ty * 4 + i) * 512 + bn + tx * 4) = o;
    }
}

// ---------------- K2: persistent recurrent scan (one barrier/step) ----------------
// 128 blocks = 16 b-groups (4 rows) x 8 h-slices (64 cols). Each block computes its
// (4b x 64h) tile with FULL K=512 (split-K inside the block via SMEM reduce).
// Weight slice (128KB) persistent in SMEM. No global partials, no gate exchange.
__global__ __launch_bounds__(256, 1) void k_recur(
    const float* __restrict__ input,
    const float* __restrict__ hidden,
    const float* __restrict__ zw_w, const float* __restrict__ zw_b,
    const float* __restrict__ zu_w, const float* __restrict__ zu_b,
    const float* __restrict__ rw_w, const float* __restrict__ rw_b,
    const float* __restrict__ ru_w, const float* __restrict__ ru_b,
    const float* __restrict__ hu_w, const float* __restrict__ hu_b,
    float* __restrict__ out,          // [T][B][H]: xn on entry, h_t on exit
    float* __restrict__ hfinal, int write_final)
{
    extern __shared__ float smem[];
    float* w_s  = smem + W_OFF;       // [k][j] j=0..63, stride 68
    float* h_s  = smem + H_OFF;       // [b][k] stride 520
    float* red_s = smem + RED_OFF;    // [kc][b][h] 16x4x64
    float* zu_s = smem + ZU_OFF;
    float* ru_s = smem + RU_OFF;
    float* xz_s = smem + XZ_OFF;      // [t*4+b]
    float* xr_s = smem + XR_OFF;
    float* gz_s = smem + GZ_OFF;      // [b*16+kc]
    float* gr_s = smem + GR_OFF;

    const int tid = threadIdx.x;
    const int bid = blockIdx.x;
    const int bg = bid >> 3;          // b-group: rows [bg*4, bg*4+4)
    const int hg = bid & 7;           // h-slice: cols [hg*64, hg*64+64)
    const int b0 = bg * 4;
    const int h0 = hg * 64;
    const int kcg = tid >> 4;         // k-chunk 0..15 (32 k each)
    const int tx = tid & 15;          // h-quad 0..15

    // persistent weight slice (transposed): w_s[k*68 + j] = hu_w[h0+j][k]
    for (int e = tid; e < 32768; e += 256) {
        int j = e >> 9, k = e & 511;
        w_s[k * 68 + j] = hu_w[(size_t)(h0 + j) * 512 + k];
    }
    for (int e = tid; e < 512; e += 256) {
        zu_s[e] = zu_w[e];
        ru_s[e] = ru_w[e];
    }
    const float zub = zu_b[0], rub = ru_b[0];
    const float zwb = zw_b[0], rwb = rw_b[0];

    // preamble: hg==0 blocks compute xz/xr for their 4 b-rows, all t
    if (hg == 0) {
        float* zw_s = red_s;          // reuse reduce buffer
        float* rw_s = red_s + 512;
        for (int e = tid; e < 512; e += 256) {
            zw_s[e] = zw_w[e];
            rw_s[e] = rw_w[e];
        }
        __syncthreads();
        for (int e = tid; e < 2048; e += 256) {
            int t = e >> 2, b = e & 3;
            const float4* ip = (const float4*)(input + ((size_t)t * 64 + b0 + b) * 512);
            float az = 0.f, ar = 0.f;
#pragma unroll 8
            for (int i = 0; i < 128; i++) {
                float4 v = ip[i];
                float4 zz = *(float4*)&zw_s[i * 4];
                float4 rr = *(float4*)&rw_s[i * 4];
                az += v.x * zz.x + v.y * zz.y + v.z * zz.z + v.w * zz.w;
                ar += v.x * rr.x + v.y * rr.y + v.z * rr.z + v.w * rr.w;
            }
            g_xz[t * 64 + b0 + b] = az + zwb;
            g_xr[t * 64 + b0 + b] = ar + rwb;
        }
    }
    gsync(tid, NBLK);

    // copy this block's gate-x slice to SMEM
    for (int e = tid; e < 2048; e += 256) {
        int t = e >> 2, b = e & 3;
        xz_s[e] = __ldcg(&g_xz[t * 64 + b0 + b]);
        xr_s[e] = __ldcg(&g_xr[t * 64 + b0 + b]);
    }

    // update-element constants (thread owns element (ub, uh) of the tile)
    const int ub = tid >> 6;          // 0..3
    const int uh = tid & 63;          // 0..63
    const float hub = hu_b[h0 + uh];
    float hreg = 0.f;
    __syncthreads();

    for (int t = 0; t < T_DIM; t++) {
        const float* hprev = (t == 0) ? hidden : (out + (size_t)(t - 1) * BH);

        // prefetch this thread's xn
        float xn = __ldcg(out + (size_t)t * BH + (size_t)(b0 + ub) * 512 + h0 + uh);

        // phase 1: load h rows [4 b][512 k] (512 float4, 2 per thread)
#pragma unroll
        for (int i = 0; i < 2; i++) {
            int e4 = tid + i * 256;
            int b = e4 >> 7, kq = e4 & 127;
            float4 v = __ldcg((const float4*)(hprev + (size_t)(b0 + b) * 512 + kq * 4));
            *(float4*)&h_s[b * 520 + kq * 4] = v;
        }
        __syncthreads();

        // phase 2a: gate-u partials (64 threads: (b, kc))
        if (tid < 64) {
            int b = tid & 3, kc2 = tid >> 2;
            float az = 0.f, ar = 0.f;
#pragma unroll
            for (int k = kc2 * 32; k < kc2 * 32 + 32; k++) {
                float hv = h_s[b * 520 + k];
                az += hv * zu_s[k];
                ar += hv * ru_s[k];
            }
            gz_s[b * 16 + kc2] = az;
            gr_s[b * 16 + kc2] = ar;
        }

        // phase 2b: matvec 4b x 4h x 32k per thread (f32x2)
        {
            unsigned long long acc[4][2] = {};
            const int kb = kcg * 32;
#pragma unroll
            for (int k = 0; k < 32; k++) {
                ulonglong2 w2 = *(ulonglong2*)&w_s[(kb + k) * 68 + tx * 4];
                unsigned long long h0p = pk2(h_s[0 * 520 + kb + k]);
                unsigned long long h1p = pk2(h_s[1 * 520 + kb + k]);
                unsigned long long h2p = pk2(h_s[2 * 520 + kb + k]);
                unsigned long long h3p = pk2(h_s[3 * 520 + kb + k]);
                fma2(acc[0][0], h0p, w2.x); fma2(acc[0][1], h0p, w2.y);
                fma2(acc[1][0], h1p, w2.x); fma2(acc[1][1], h1p, w2.y);
                fma2(acc[2][0], h2p, w2.x); fma2(acc[2][1], h2p, w2.y);
                fma2(acc[3][0], h3p, w2.x); fma2(acc[3][1], h3p, w2.y);
            }
#pragma unroll
            for (int b = 0; b < 4; b++) {
                float x0, x1, x2, x3;
                unpk(acc[b][0], x0, x1);
                unpk(acc[b][1], x2, x3);
                *(float4*)&red_s[kcg * 256 + b * 64 + tx * 4] =
                    make_float4(x0, x1, x2, x3);
            }
        }
        __syncthreads();

        // phase 3: reduce k-partials + gates + update (1 element/thread)
        {
            float m = hub;
#pragma unroll
            for (int kc = 0; kc < 16; kc++)
                m += red_s[kc * 256 + ub * 64 + uh];
            float az = xz_s[t * 4 + ub] + zub;
            float ar = xr_s[t * 4 + ub] + rub;
#pragma unroll
            for (int kc = 0; kc < 16; kc++) {
                az += gz_s[ub * 16 + kc];
                ar += gr_s[ub * 16 + kc];
            }
            float z = 1.0f / (1.0f + __expf(-az));
            float r = 1.0f / (1.0f + __expf(-ar));
            float hold = h_s[ub * 520 + h0 + uh];
            float arg = xn + m * r;
            arg = fminf(fmaxf(arg, -15.0f), 15.0f);
            float e2 = __expf(2.0f * arg);
            float n = 1.0f - 2.0f / (e2 + 1.0f);
            hreg = (1.0f - z) * n + z * hold;
            out[(size_t)t * BH + (size_t)(b0 + ub) * 512 + h0 + uh] = hreg;
        }

        gsync(tid, (unsigned int)NBLK * (t + 2));
    }

    if (write_final)
        hfinal[(size_t)(b0 + ub) * 512 + h0 + uh] = hreg;

    // final arrival + counter reset for graph replay
    __syncthreads();
    if (tid == 0) {
        arrive_rel();                        // total arrivals: NBLK*(T+2)
        if (bid == 0) {
            unsigned int fin = (unsigned int)NBLK * (T_DIM + 2);
            while (ld_acq_ctr() < fin) { }
            unsigned int* p = &g_ctr;
            asm volatile("st.relaxed.gpu.global.u32 [%0], 0;" :: "l"(p) : "memory");
        }
    }
}

// ---------------- launcher ----------------
extern "C" void kernel_launch(void* const* d_in, const int* in_sizes, int n_in,
                              void* d_out, int out_size)
{
    const float* input  = (const float*)d_in[0];
    const float* hidden = (const float*)d_in[1];
    const float* zt_w_w = (const float*)d_in[2];
    const float* zt_w_b = (const float*)d_in[3];
    const float* zt_u_w = (const float*)d_in[4];
    const float* zt_u_b = (const float*)d_in[5];
    const float* rt_w_w = (const float*)d_in[6];
    const float* rt_w_b = (const float*)d_in[7];
    const float* rt_u_w = (const float*)d_in[8];
    const float* rt_u_b = (const float*)d_in[9];
    const float* h_w_w  = (const float*)d_in[10];
    const float* h_w_b  = (const float*)d_in[11];
    const float* h_u_w  = (const float*)d_in[12];
    const float* h_u_b  = (const float*)d_in[13];

    float* out = (float*)d_out;
    int wf = (out_size >= T_DIM * BH + BH) ? 1 : 0;
    float* hfin = out + (size_t)T_DIM * BH;

    cudaFuncSetAttribute(k_recur, cudaFuncAttributeMaxDynamicSharedMemorySize,
                         SMEM_BYTES);

    k_xn<<<dim3(8, 512), 256>>>(input, h_w_w, h_w_b, out);
    k_recur<<<NBLK, 256, SMEM_BYTES>>>(input, hidden,
                                       zt_w_w, zt_w_b, zt_u_w, zt_u_b,
                                       rt_w_w, rt_w_b, rt_u_w, rt_u_b,
                                       h_u_w, h_u_b, out, hfin, wf);
}